// round 15
// baseline (speedup 1.0000x reference)
#include <cuda_runtime.h>
#include <cuda_fp16.h>
#include <cstdint>
#include <cstddef>

// Problem constants
#define BATCH   4
#define S_LEN   2048
#define D_MODEL 1024
#define NHEAD   16
#define HEAD_D  64
#define TDQ     (3 * D_MODEL)          // 3072
#define M_ROWS  (BATCH * S_LEN)        // 8192
#define KDIM    D_MODEL                // 1024
#define BH      (BATCH * NHEAD)        // 64

// ---------------------------------------------------------------------------
// Scratch (__device__ globals; allocation-free rule)
// ---------------------------------------------------------------------------
__device__ __align__(128) __half g_x16  [(size_t)M_ROWS * KDIM];
__device__ __align__(128) __half g_wq16 [(size_t)TDQ    * KDIM];
__device__ __align__(128) __half g_wo16 [(size_t)D_MODEL* KDIM];
__device__ __align__(128) __half g_qkv16[(size_t)M_ROWS * TDQ];
__device__ __align__(128) __half g_at16 [(size_t)M_ROWS * D_MODEL];
__device__ unsigned int g_ctr[2];      // persistent-GEMM tile counters

// ---------------------------------------------------------------------------
// Helpers
// ---------------------------------------------------------------------------
__device__ __forceinline__ uint32_t smem_u32(const void* p) {
    uint32_t a;
    asm("{ .reg .u64 t; cvta.to.shared.u64 t, %1; cvt.u32.u64 %0, t; }"
        : "=r"(a) : "l"(p));
    return a;
}

#define CP_ASYNC16(saddr, gptr) \
    asm volatile("cp.async.cg.shared.global [%0], [%1], 16;" :: "r"(saddr), "l"(gptr))
#define CP_COMMIT() asm volatile("cp.async.commit_group;" ::: "memory")
#define CP_WAIT0()  asm volatile("cp.async.wait_group 0;" ::: "memory")
#define CP_WAIT1()  asm volatile("cp.async.wait_group 1;" ::: "memory")

__device__ __forceinline__ void ldsm4(uint32_t* r, uint32_t addr) {
    asm volatile("ldmatrix.sync.aligned.m8n8.x4.shared.b16 {%0,%1,%2,%3}, [%4];"
                 : "=r"(r[0]), "=r"(r[1]), "=r"(r[2]), "=r"(r[3]) : "r"(addr));
}
__device__ __forceinline__ void ldsm4t(uint32_t* r, uint32_t addr) {
    asm volatile("ldmatrix.sync.aligned.m8n8.x4.trans.shared.b16 {%0,%1,%2,%3}, [%4];"
                 : "=r"(r[0]), "=r"(r[1]), "=r"(r[2]), "=r"(r[3]) : "r"(addr));
}
__device__ __forceinline__ void mma16816h(float* d, const uint32_t* a,
                                          uint32_t b0, uint32_t b1) {
    asm volatile(
        "mma.sync.aligned.m16n8k16.row.col.f32.f16.f16.f32 "
        "{%0,%1,%2,%3}, {%4,%5,%6,%7}, {%8,%9}, {%0,%1,%2,%3};"
        : "+f"(d[0]), "+f"(d[1]), "+f"(d[2]), "+f"(d[3])
        : "r"(a[0]), "r"(a[1]), "r"(a[2]), "r"(a[3]), "r"(b0), "r"(b1));
}
__device__ __forceinline__ uint32_t pack_h2(float x, float y) {
    __half2 h = __floats2half2_rn(x, y);
    return *(uint32_t*)&h;
}

// ---------------------------------------------------------------------------
// Fused fp32 -> fp16 convert for x, w_qkv, w_o; also resets tile counters.
// ---------------------------------------------------------------------------
#define N4_X  (M_ROWS * KDIM / 4)       // 2097152
#define N4_WQ (TDQ * KDIM / 4)          // 786432
#define N4_WO (D_MODEL * KDIM / 4)      // 262144
#define N4_TOTAL (N4_X + N4_WQ + N4_WO)

__global__ void __launch_bounds__(256)
cvt16_all(const float4* __restrict__ x, const float4* __restrict__ wq,
          const float4* __restrict__ wo,
          uint2* __restrict__ x16, uint2* __restrict__ wq16, uint2* __restrict__ wo16)
{
    int i = blockIdx.x * blockDim.x + threadIdx.x;
    if (i == 0) { g_ctr[0] = 0; g_ctr[1] = 0; }
    if (i >= N4_TOTAL) return;
    const float4* src;
    uint2* dst;
    int j;
    if (i < N4_X)             { src = x;  dst = x16;  j = i; }
    else if (i < N4_X + N4_WQ){ src = wq; dst = wq16; j = i - N4_X; }
    else                      { src = wo; dst = wo16; j = i - N4_X - N4_WQ; }
    float4 v = src[j];
    uint2 o;
    o.x = pack_h2(v.x, v.y);
    o.y = pack_h2(v.z, v.w);
    dst[j] = o;
}

// ---------------------------------------------------------------------------
// Persistent fp16 HMMA GEMM (NT) — exact R14 config (proven best).
// 128x128 CTA tile, BK=64, 8 warps 2(M)x4(N), 3-stage cp.async, 2 CTAs/SM.
// ---------------------------------------------------------------------------
#define ROWB   144                      // 128B data + 16 pad
#define A_ARR  (128 * ROWB)             // 18432
#define B_ARR  (128 * ROWB)             // 18432
#define STAGE_B (A_ARR + B_ARR)         // 36864
#define GEMM_SMEM (3 * STAGE_B)         // 110592 -> 2 CTAs/SM

__global__ void __launch_bounds__(256, 2)
gemm_hmma(const __half* __restrict__ A, const __half* __restrict__ B,
          const float* __restrict__ bias, void* __restrict__ Cv,
          int M, int N, int K, int half_out, int ctr_idx)
{
    extern __shared__ char sm[];
    __shared__ unsigned int s_tile;
    const int tid  = threadIdx.x;
    const int wid  = tid >> 5;
    const int lane = tid & 31;
    const int wm   = wid & 1;           // 0..1 (M)
    const int wn   = wid >> 1;          // 0..3 (N)

    const uint32_t smb = smem_u32(sm);
    const int NBX = N / 128;
    const unsigned int ntiles = (unsigned int)((M / 128) * NBX);

    const uint32_t aoff = (uint32_t)((wm * 64 + (lane & 15)) * ROWB + (lane >> 4) * 16);
    const uint32_t boff = (uint32_t)((wn * 32 + (lane & 15)) * ROWB + (lane >> 4) * 16);
    const int NC = K / 64;

    for (;;) {
        if (tid == 0) s_tile = atomicAdd(&g_ctr[ctr_idx], 1u);
        __syncthreads();
        const unsigned int tile = s_tile;
        if (tile >= ntiles) break;
        const int row0 = (int)(tile / NBX) * 128;
        const int col0 = (int)(tile % NBX) * 128;

        auto ld_chunk = [&](int i, int stage) {
            const int k0 = i * 64;
            uint32_t sb = smb + stage * STAGE_B;
            #pragma unroll
            for (int rep = 0; rep < 4; rep++) {
                int idx = tid + rep * 256;
                int row = idx >> 3, ch = idx & 7;
                size_t go = (size_t)(row0 + row) * K + k0 + ch * 8;
                CP_ASYNC16(sb + row * ROWB + ch * 16, A + go);
            }
            #pragma unroll
            for (int rep = 0; rep < 4; rep++) {
                int idx = tid + rep * 256;
                int row = idx >> 3, ch = idx & 7;
                size_t go = (size_t)(col0 + row) * K + k0 + ch * 8;
                CP_ASYNC16(sb + A_ARR + row * ROWB + ch * 16, B + go);
            }
        };

        float acc[4][4][4];
        #pragma unroll
        for (int i = 0; i < 4; i++)
            #pragma unroll
            for (int j = 0; j < 4; j++)
                #pragma unroll
                for (int v = 0; v < 4; v++) acc[i][j][v] = 0.f;

        ld_chunk(0, 0); CP_COMMIT();
        ld_chunk(1, 1); CP_COMMIT();

        int st = 0;
        for (int i = 0; i < NC; i++) {
            if (i < NC - 1) { CP_WAIT1(); } else { CP_WAIT0(); }
            __syncthreads();
            if (i + 2 < NC) {
                int s2 = st + 2; if (s2 >= 3) s2 -= 3;
                ld_chunk(i + 2, s2);
                CP_COMMIT();
            }

            const uint32_t sA = smb + st * STAGE_B;
            const uint32_t sB = sA + A_ARR;

            #pragma unroll
            for (int ks = 0; ks < 4; ks++) {
                uint32_t ah[4][4], bb[2][4];
                #pragma unroll
                for (int fi = 0; fi < 4; fi++)
                    ldsm4(ah[fi], sA + aoff + fi * 16 * ROWB + ks * 32);
                #pragma unroll
                for (int fp = 0; fp < 2; fp++)
                    ldsm4(bb[fp], sB + boff + fp * 16 * ROWB + ks * 32);
                #pragma unroll
                for (int fi = 0; fi < 4; fi++)
                    #pragma unroll
                    for (int fp = 0; fp < 2; fp++) {
                        mma16816h(acc[fi][2 * fp],     ah[fi], bb[fp][0], bb[fp][2]);
                        mma16816h(acc[fi][2 * fp + 1], ah[fi], bb[fp][1], bb[fp][3]);
                    }
            }
            if (++st == 3) st = 0;
        }

        if (half_out) {
            __half* C = (__half*)Cv;
            #pragma unroll
            for (int fi = 0; fi < 4; fi++) {
                const int r = row0 + wm * 64 + fi * 16 + (lane >> 2);
                #pragma unroll
                for (int fj = 0; fj < 4; fj++) {
                    const int cc = col0 + wn * 32 + fj * 8 + (lane & 3) * 2;
                    float2 bbv = *(const float2*)&bias[cc];
                    *(uint32_t*)&C[(size_t)r * N + cc] =
                        pack_h2(acc[fi][fj][0] + bbv.x, acc[fi][fj][1] + bbv.y);
                    *(uint32_t*)&C[(size_t)(r + 8) * N + cc] =
                        pack_h2(acc[fi][fj][2] + bbv.x, acc[fi][fj][3] + bbv.y);
                }
            }
        } else {
            float* C = (float*)Cv;
            #pragma unroll
            for (int fi = 0; fi < 4; fi++) {
                const int r = row0 + wm * 64 + fi * 16 + (lane >> 2);
                #pragma unroll
                for (int fj = 0; fj < 4; fj++) {
                    const int cc = col0 + wn * 32 + fj * 8 + (lane & 3) * 2;
                    float2 bbv = *(const float2*)&bias[cc];
                    float2 v0 = make_float2(acc[fi][fj][0] + bbv.x, acc[fi][fj][1] + bbv.y);
                    float2 v1 = make_float2(acc[fi][fj][2] + bbv.x, acc[fi][fj][3] + bbv.y);
                    *(float2*)&C[(size_t)r * N + cc]       = v0;
                    *(float2*)&C[(size_t)(r + 8) * N + cc] = v1;
                }
            }
        }
    }
}

// ---------------------------------------------------------------------------
// Flash attention, fp16 HMMA. 256 q rows/CTA (512 threads, 16 warps x 16
// rows), 64-key tiles, 3-stage cp.async. KV cp.async bytes per CTA-tile are
// fixed, so doubling rows/CTA halves total cp.async issue (the R14 binder).
// ---------------------------------------------------------------------------
#define ATHREADS 512
#define QROW     144
#define Q_ARR    (256 * QROW)          // 36864
#define KVROW    272                   // 256B data + 16 pad
#define KV_STAGE (64 * KVROW)          // 17408
#define ATTN_SMEM (Q_ARR + 3 * KV_STAGE)   // 89088

__global__ void __launch_bounds__(ATHREADS, 1)
attn_mma(const __half* __restrict__ qkv, __half* __restrict__ outp)
{
    extern __shared__ char sm[];
    const uint32_t smb = smem_u32(sm);
    const int tid  = threadIdx.x;
    const int wid  = tid >> 5;          // 0..15, each owns 16 q rows
    const int lane = tid & 31;
    const int bh = blockIdx.y;
    const int qb = blockIdx.x;          // 256-row q block
    const int b  = bh >> 4;
    const int h  = bh & 15;

    const __half* Qp  = qkv + ((size_t)(b * S_LEN + qb * 256)) * TDQ + h * 3 * HEAD_D;
    const __half* KVb = qkv + ((size_t)(b * S_LEN)) * TDQ + h * 3 * HEAD_D + HEAD_D;

    auto ld_tile = [&](int kt, int st) {
        const int k0 = kt * 64;
        const uint32_t sb = smb + Q_ARR + st * KV_STAGE;
        #pragma unroll
        for (int rep = 0; rep < 2; rep++) {
            int idx = tid + rep * ATHREADS;   // 0..1023
            int row = idx >> 4;               // 0..63
            int ch  = idx & 15;               // 16 x 16B = 256B (K then V)
            CP_ASYNC16(sb + row * KVROW + ch * 16,
                       KVb + (size_t)(k0 + row) * TDQ + ch * 8);
        }
    };

    // Q: 256 rows x 8 chunks = 2048 ops
    #pragma unroll
    for (int rep = 0; rep < 4; rep++) {
        int idx = tid + rep * ATHREADS;
        int row = idx >> 3;                   // 0..255
        int ch  = idx & 7;
        CP_ASYNC16(smb + row * QROW + ch * 16, Qp + (size_t)row * TDQ + ch * 8);
    }
    ld_tile(0, 0);
    CP_COMMIT();
    ld_tile(1, 1);
    CP_COMMIT();

    CP_WAIT1();
    __syncthreads();

    const uint32_t qbase = smb + (uint32_t)((wid * 16 + (lane & 15)) * QROW
                                            + (lane >> 4) * 16);
    uint32_t qf[4][4];
    const __half2 sc = __half2half2(__float2half(0.125f));
    #pragma unroll
    for (int kk = 0; kk < 4; kk++) {
        ldsm4(qf[kk], qbase + kk * 32);
        #pragma unroll
        for (int r = 0; r < 4; r++) {
            __half2 hv = *(__half2*)&qf[kk][r];
            hv = __hmul2(hv, sc);
            qf[kk][r] = *(uint32_t*)&hv;
        }
    }

    float o[8][4];
    #pragma unroll
    for (int nf = 0; nf < 8; nf++)
        #pragma unroll
        for (int v = 0; v < 4; v++) o[nf][v] = 0.f;
    float m0 = -1e30f, m1 = -1e30f, l0 = 0.f, l1 = 0.f;

    const uint32_t bo_k = (uint32_t)((lane & 15) * KVROW + (lane >> 4) * 16);
    const uint32_t bo_v = (uint32_t)((((lane & 7) | (((lane >> 3) & 1) << 3))) * KVROW
                                     + (lane >> 4) * 16 + 128);
    const int NT = S_LEN / 64;

    int st = 0;
    for (int kt = 0; kt < NT; kt++) {
        if (kt < NT - 1) { CP_WAIT1(); } else { CP_WAIT0(); }
        __syncthreads();
        if (kt + 2 < NT) {
            int s2 = st + 2; if (s2 >= 3) s2 -= 3;
            ld_tile(kt + 2, s2);
            CP_COMMIT();
        }

        const uint32_t base_kv = smb + Q_ARR + st * KV_STAGE;

        float s_[8][4];
        #pragma unroll
        for (int nf = 0; nf < 8; nf++)
            #pragma unroll
            for (int v = 0; v < 4; v++) s_[nf][v] = 0.f;

        #pragma unroll
        for (int np = 0; np < 4; np++) {
            #pragma unroll
            for (int kk = 0; kk < 4; kk++) {
                uint32_t kb[4];
                ldsm4(kb, base_kv + bo_k + np * 16 * KVROW + kk * 32);
                mma16816h(s_[2 * np],     qf[kk], kb[0], kb[2]);
                mma16816h(s_[2 * np + 1], qf[kk], kb[1], kb[3]);
            }
        }

        float tm0 = -1e30f, tm1 = -1e30f;
        #pragma unroll
        for (int nf = 0; nf < 8; nf++) {
            tm0 = fmaxf(tm0, fmaxf(s_[nf][0], s_[nf][1]));
            tm1 = fmaxf(tm1, fmaxf(s_[nf][2], s_[nf][3]));
        }
        tm0 = fmaxf(tm0, __shfl_xor_sync(0xffffffffu, tm0, 1));
        tm0 = fmaxf(tm0, __shfl_xor_sync(0xffffffffu, tm0, 2));
        tm1 = fmaxf(tm1, __shfl_xor_sync(0xffffffffu, tm1, 1));
        tm1 = fmaxf(tm1, __shfl_xor_sync(0xffffffffu, tm1, 2));

        const float mn0 = fmaxf(m0, tm0);
        const float mn1 = fmaxf(m1, tm1);
        const float a0 = __expf(m0 - mn0);
        const float a1 = __expf(m1 - mn1);
        m0 = mn0; m1 = mn1;

        float sum0 = 0.f, sum1 = 0.f;
        #pragma unroll
        for (int nf = 0; nf < 8; nf++) {
            s_[nf][0] = __expf(s_[nf][0] - m0);
            s_[nf][1] = __expf(s_[nf][1] - m0);
            s_[nf][2] = __expf(s_[nf][2] - m1);
            s_[nf][3] = __expf(s_[nf][3] - m1);
            sum0 += s_[nf][0] + s_[nf][1];
            sum1 += s_[nf][2] + s_[nf][3];
        }
        sum0 += __shfl_xor_sync(0xffffffffu, sum0, 1);
        sum0 += __shfl_xor_sync(0xffffffffu, sum0, 2);
        sum1 += __shfl_xor_sync(0xffffffffu, sum1, 1);
        sum1 += __shfl_xor_sync(0xffffffffu, sum1, 2);
        l0 = l0 * a0 + sum0;
        l1 = l1 * a1 + sum1;

        #pragma unroll
        for (int nf = 0; nf < 8; nf++) {
            o[nf][0] *= a0; o[nf][1] *= a0;
            o[nf][2] *= a1; o[nf][3] *= a1;
        }

        uint32_t pa[4][4];
        #pragma unroll
        for (int kk = 0; kk < 4; kk++) {
            const int n0 = 2 * kk, n1 = 2 * kk + 1;
            pa[kk][0] = pack_h2(s_[n0][0], s_[n0][1]);
            pa[kk][1] = pack_h2(s_[n0][2], s_[n0][3]);
            pa[kk][2] = pack_h2(s_[n1][0], s_[n1][1]);
            pa[kk][3] = pack_h2(s_[n1][2], s_[n1][3]);
        }

        #pragma unroll
        for (int dd = 0; dd < 4; dd++) {
            #pragma unroll
            for (int kk = 0; kk < 4; kk++) {
                uint32_t vb[4];
                ldsm4t(vb, base_kv + bo_v + kk * 16 * KVROW + dd * 32);
                mma16816h(o[2 * dd],     pa[kk], vb[0], vb[1]);
                mma16816h(o[2 * dd + 1], pa[kk], vb[2], vb[3]);
            }
        }

        if (++st == 3) st = 0;
    }

    const float inv0 = 1.f / l0;
    const float inv1 = 1.f / l1;
    const int r0 = qb * 256 + wid * 16 + (lane >> 2);
    const size_t tok0 = (size_t)(b * S_LEN + r0) * D_MODEL;
    const size_t tok1 = (size_t)(b * S_LEN + r0 + 8) * D_MODEL;
    #pragma unroll
    for (int nf = 0; nf < 8; nf++) {
        const int col = h * HEAD_D + nf * 8 + (lane & 3) * 2;
        *(uint32_t*)(outp + tok0 + col) = pack_h2(o[nf][0] * inv0, o[nf][1] * inv0);
        *(uint32_t*)(outp + tok1 + col) = pack_h2(o[nf][2] * inv1, o[nf][3] * inv1);
    }
}

// ---------------------------------------------------------------------------
extern "C" void kernel_launch(void* const* d_in, const int* in_sizes, int n_in,
                              void* d_out, int out_size)
{
    const float* x     = (const float*)d_in[0];
    const float* w_qkv = (const float*)d_in[1];
    const float* b_qkv = (const float*)d_in[2];
    const float* w_o   = (const float*)d_in[3];
    const float* b_o   = (const float*)d_in[4];
    float* out = (float*)d_out;

    __half *x16, *wq16, *wo16, *qkv16, *at16;
    cudaGetSymbolAddress((void**)&x16,   g_x16);
    cudaGetSymbolAddress((void**)&wq16,  g_wq16);
    cudaGetSymbolAddress((void**)&wo16,  g_wo16);
    cudaGetSymbolAddress((void**)&qkv16, g_qkv16);
    cudaGetSymbolAddress((void**)&at16,  g_at16);

    cudaFuncSetAttribute(gemm_hmma, cudaFuncAttributeMaxDynamicSharedMemorySize, GEMM_SMEM);
    cudaFuncSetAttribute(attn_mma,  cudaFuncAttributeMaxDynamicSharedMemorySize, ATTN_SMEM);

    // fused fp32 -> fp16 converts + counter reset
    cvt16_all<<<(N4_TOTAL + 255) / 256, 256>>>(
        (const float4*)x, (const float4*)w_qkv, (const float4*)w_o,
        (uint2*)x16, (uint2*)wq16, (uint2*)wo16);

    // 1) QKV projection -> fp16 (persistent, counter 0)
    {
        int ntiles = (M_ROWS / 128) * (TDQ / 128);     // 1536
        gemm_hmma<<<ntiles, 256, GEMM_SMEM>>>(x16, wq16, b_qkv, qkv16,
                                              M_ROWS, TDQ, KDIM, 1, 0);
    }
    // 2) tensor-core flash attention -> fp16 [token][1024]
    {
        dim3 grid(S_LEN / 256, BH);                    // 8 x 64 = 512 CTAs
        attn_mma<<<grid, ATHREADS, ATTN_SMEM>>>(qkv16, at16);
    }
    // 3) output projection -> fp32 (persistent, counter 1)
    {
        int ntiles = (M_ROWS / 128) * (D_MODEL / 128); // 512
        gemm_hmma<<<ntiles, 256, GEMM_SMEM>>>(at16, wo16, b_o, out,
                                              M_ROWS, D_MODEL, KDIM, 0, 1);
    }
}

// round 16
// speedup vs baseline: 1.0574x; 1.0574x over previous
#include <cuda_runtime.h>
#include <cuda_fp16.h>
#include <cstdint>
#include <cstddef>

// Problem constants
#define BATCH   4
#define S_LEN   2048
#define D_MODEL 1024
#define NHEAD   16
#define HEAD_D  64
#define TDQ     (3 * D_MODEL)          // 3072
#define M_ROWS  (BATCH * S_LEN)        // 8192
#define KDIM    D_MODEL                // 1024
#define BH      (BATCH * NHEAD)        // 64

// ---------------------------------------------------------------------------
// Scratch (__device__ globals; allocation-free rule)
// ---------------------------------------------------------------------------
__device__ __align__(128) __half g_x16  [(size_t)M_ROWS * KDIM];
__device__ __align__(128) __half g_wq16 [(size_t)TDQ    * KDIM];
__device__ __align__(128) __half g_wo16 [(size_t)D_MODEL* KDIM];
__device__ __align__(128) __half g_qkv16[(size_t)M_ROWS * TDQ];
__device__ __align__(128) __half g_at16 [(size_t)M_ROWS * D_MODEL];
__device__ unsigned int g_ctr[3];      // persistent tile counters (gemm1, gemm2, attn)

// ---------------------------------------------------------------------------
// Helpers
// ---------------------------------------------------------------------------
__device__ __forceinline__ uint32_t smem_u32(const void* p) {
    uint32_t a;
    asm("{ .reg .u64 t; cvta.to.shared.u64 t, %1; cvt.u32.u64 %0, t; }"
        : "=r"(a) : "l"(p));
    return a;
}

#define CP_ASYNC16(saddr, gptr) \
    asm volatile("cp.async.cg.shared.global [%0], [%1], 16;" :: "r"(saddr), "l"(gptr))
#define CP_COMMIT() asm volatile("cp.async.commit_group;" ::: "memory")
#define CP_WAIT0()  asm volatile("cp.async.wait_group 0;" ::: "memory")
#define CP_WAIT1()  asm volatile("cp.async.wait_group 1;" ::: "memory")

__device__ __forceinline__ void ldsm4(uint32_t* r, uint32_t addr) {
    asm volatile("ldmatrix.sync.aligned.m8n8.x4.shared.b16 {%0,%1,%2,%3}, [%4];"
                 : "=r"(r[0]), "=r"(r[1]), "=r"(r[2]), "=r"(r[3]) : "r"(addr));
}
__device__ __forceinline__ void ldsm4t(uint32_t* r, uint32_t addr) {
    asm volatile("ldmatrix.sync.aligned.m8n8.x4.trans.shared.b16 {%0,%1,%2,%3}, [%4];"
                 : "=r"(r[0]), "=r"(r[1]), "=r"(r[2]), "=r"(r[3]) : "r"(addr));
}
__device__ __forceinline__ void mma16816h(float* d, const uint32_t* a,
                                          uint32_t b0, uint32_t b1) {
    asm volatile(
        "mma.sync.aligned.m16n8k16.row.col.f32.f16.f16.f32 "
        "{%0,%1,%2,%3}, {%4,%5,%6,%7}, {%8,%9}, {%0,%1,%2,%3};"
        : "+f"(d[0]), "+f"(d[1]), "+f"(d[2]), "+f"(d[3])
        : "r"(a[0]), "r"(a[1]), "r"(a[2]), "r"(a[3]), "r"(b0), "r"(b1));
}
__device__ __forceinline__ uint32_t pack_h2(float x, float y) {
    __half2 h = __floats2half2_rn(x, y);
    return *(uint32_t*)&h;
}

// ---------------------------------------------------------------------------
// Fused fp32 -> fp16 convert for x, w_qkv, w_o; also resets tile counters.
// ---------------------------------------------------------------------------
#define N4_X  (M_ROWS * KDIM / 4)       // 2097152
#define N4_WQ (TDQ * KDIM / 4)          // 786432
#define N4_WO (D_MODEL * KDIM / 4)      // 262144
#define N4_TOTAL (N4_X + N4_WQ + N4_WO)

__global__ void __launch_bounds__(256)
cvt16_all(const float4* __restrict__ x, const float4* __restrict__ wq,
          const float4* __restrict__ wo,
          uint2* __restrict__ x16, uint2* __restrict__ wq16, uint2* __restrict__ wo16)
{
    int i = blockIdx.x * blockDim.x + threadIdx.x;
    if (i == 0) { g_ctr[0] = 0; g_ctr[1] = 0; g_ctr[2] = 0; }
    if (i >= N4_TOTAL) return;
    const float4* src;
    uint2* dst;
    int j;
    if (i < N4_X)             { src = x;  dst = x16;  j = i; }
    else if (i < N4_X + N4_WQ){ src = wq; dst = wq16; j = i - N4_X; }
    else                      { src = wo; dst = wo16; j = i - N4_X - N4_WQ; }
    float4 v = src[j];
    uint2 o;
    o.x = pack_h2(v.x, v.y);
    o.y = pack_h2(v.z, v.w);
    dst[j] = o;
}

// ---------------------------------------------------------------------------
// Persistent fp16 HMMA GEMM (NT) — exact R14 config (proven best).
// 128x128 CTA tile, BK=64, 8 warps 2(M)x4(N), 3-stage cp.async, 2 CTAs/SM.
// ---------------------------------------------------------------------------
#define ROWB   144                      // 128B data + 16 pad
#define A_ARR  (128 * ROWB)             // 18432
#define B_ARR  (128 * ROWB)             // 18432
#define STAGE_B (A_ARR + B_ARR)         // 36864
#define GEMM_SMEM (3 * STAGE_B)         // 110592 -> 2 CTAs/SM

__global__ void __launch_bounds__(256, 2)
gemm_hmma(const __half* __restrict__ A, const __half* __restrict__ B,
          const float* __restrict__ bias, void* __restrict__ Cv,
          int M, int N, int K, int half_out, int ctr_idx)
{
    extern __shared__ char sm[];
    __shared__ unsigned int s_tile;
    const int tid  = threadIdx.x;
    const int wid  = tid >> 5;
    const int lane = tid & 31;
    const int wm   = wid & 1;           // 0..1 (M)
    const int wn   = wid >> 1;          // 0..3 (N)

    const uint32_t smb = smem_u32(sm);
    const int NBX = N / 128;
    const unsigned int ntiles = (unsigned int)((M / 128) * NBX);

    const uint32_t aoff = (uint32_t)((wm * 64 + (lane & 15)) * ROWB + (lane >> 4) * 16);
    const uint32_t boff = (uint32_t)((wn * 32 + (lane & 15)) * ROWB + (lane >> 4) * 16);
    const int NC = K / 64;

    for (;;) {
        if (tid == 0) s_tile = atomicAdd(&g_ctr[ctr_idx], 1u);
        __syncthreads();
        const unsigned int tile = s_tile;
        if (tile >= ntiles) break;
        const int row0 = (int)(tile / NBX) * 128;
        const int col0 = (int)(tile % NBX) * 128;

        auto ld_chunk = [&](int i, int stage) {
            const int k0 = i * 64;
            uint32_t sb = smb + stage * STAGE_B;
            #pragma unroll
            for (int rep = 0; rep < 4; rep++) {
                int idx = tid + rep * 256;
                int row = idx >> 3, ch = idx & 7;
                size_t go = (size_t)(row0 + row) * K + k0 + ch * 8;
                CP_ASYNC16(sb + row * ROWB + ch * 16, A + go);
            }
            #pragma unroll
            for (int rep = 0; rep < 4; rep++) {
                int idx = tid + rep * 256;
                int row = idx >> 3, ch = idx & 7;
                size_t go = (size_t)(col0 + row) * K + k0 + ch * 8;
                CP_ASYNC16(sb + A_ARR + row * ROWB + ch * 16, B + go);
            }
        };

        float acc[4][4][4];
        #pragma unroll
        for (int i = 0; i < 4; i++)
            #pragma unroll
            for (int j = 0; j < 4; j++)
                #pragma unroll
                for (int v = 0; v < 4; v++) acc[i][j][v] = 0.f;

        ld_chunk(0, 0); CP_COMMIT();
        ld_chunk(1, 1); CP_COMMIT();

        int st = 0;
        for (int i = 0; i < NC; i++) {
            if (i < NC - 1) { CP_WAIT1(); } else { CP_WAIT0(); }
            __syncthreads();
            if (i + 2 < NC) {
                int s2 = st + 2; if (s2 >= 3) s2 -= 3;
                ld_chunk(i + 2, s2);
                CP_COMMIT();
            }

            const uint32_t sA = smb + st * STAGE_B;
            const uint32_t sB = sA + A_ARR;

            #pragma unroll
            for (int ks = 0; ks < 4; ks++) {
                uint32_t ah[4][4], bb[2][4];
                #pragma unroll
                for (int fi = 0; fi < 4; fi++)
                    ldsm4(ah[fi], sA + aoff + fi * 16 * ROWB + ks * 32);
                #pragma unroll
                for (int fp = 0; fp < 2; fp++)
                    ldsm4(bb[fp], sB + boff + fp * 16 * ROWB + ks * 32);
                #pragma unroll
                for (int fi = 0; fi < 4; fi++)
                    #pragma unroll
                    for (int fp = 0; fp < 2; fp++) {
                        mma16816h(acc[fi][2 * fp],     ah[fi], bb[fp][0], bb[fp][2]);
                        mma16816h(acc[fi][2 * fp + 1], ah[fi], bb[fp][1], bb[fp][3]);
                    }
            }
            if (++st == 3) st = 0;
        }

        if (half_out) {
            __half* C = (__half*)Cv;
            #pragma unroll
            for (int fi = 0; fi < 4; fi++) {
                const int r = row0 + wm * 64 + fi * 16 + (lane >> 2);
                #pragma unroll
                for (int fj = 0; fj < 4; fj++) {
                    const int cc = col0 + wn * 32 + fj * 8 + (lane & 3) * 2;
                    float2 bbv = *(const float2*)&bias[cc];
                    *(uint32_t*)&C[(size_t)r * N + cc] =
                        pack_h2(acc[fi][fj][0] + bbv.x, acc[fi][fj][1] + bbv.y);
                    *(uint32_t*)&C[(size_t)(r + 8) * N + cc] =
                        pack_h2(acc[fi][fj][2] + bbv.x, acc[fi][fj][3] + bbv.y);
                }
            }
        } else {
            float* C = (float*)Cv;
            #pragma unroll
            for (int fi = 0; fi < 4; fi++) {
                const int r = row0 + wm * 64 + fi * 16 + (lane >> 2);
                #pragma unroll
                for (int fj = 0; fj < 4; fj++) {
                    const int cc = col0 + wn * 32 + fj * 8 + (lane & 3) * 2;
                    float2 bbv = *(const float2*)&bias[cc];
                    float2 v0 = make_float2(acc[fi][fj][0] + bbv.x, acc[fi][fj][1] + bbv.y);
                    float2 v1 = make_float2(acc[fi][fj][2] + bbv.x, acc[fi][fj][3] + bbv.y);
                    *(float2*)&C[(size_t)r * N + cc]       = v0;
                    *(float2*)&C[(size_t)(r + 8) * N + cc] = v1;
                }
            }
        }
    }
}

// ---------------------------------------------------------------------------
// Flash attention, fp16 HMMA — R14 body (proven best) wrapped in a
// persistent atomic work queue (counter 2). Work item = (qb, bh):
// 128 q rows, 8 warps x 16 rows, 64-key tiles, 3-stage cp.async,
// Q/K/V straight from qkv16 (merged K+V region, V^T via ldsm4.trans),
// 2 CTAs/SM. 1024 items drain greedily -> no wave lockstep tail.
// ---------------------------------------------------------------------------
#define QROW     144
#define Q_ARR    (128 * QROW)          // 18432
#define KVROW    272                   // 256B data + 16 pad
#define KV_STAGE (64 * KVROW)          // 17408
#define ATTN_SMEM (Q_ARR + 3 * KV_STAGE)   // 70656
#define ATTN_ITEMS ((S_LEN / 128) * BH)    // 1024

__global__ void __launch_bounds__(256, 2)
attn_mma(const __half* __restrict__ qkv, __half* __restrict__ outp)
{
    extern __shared__ char sm[];
    __shared__ unsigned int s_item;
    const uint32_t smb = smem_u32(sm);
    const int tid  = threadIdx.x;
    const int wid  = tid >> 5;
    const int lane = tid & 31;

    const uint32_t qbase_off = (uint32_t)((wid * 16 + (lane & 15)) * QROW
                                          + (lane >> 4) * 16);
    const uint32_t bo_k = (uint32_t)((lane & 15) * KVROW + (lane >> 4) * 16);
    const uint32_t bo_v = (uint32_t)((((lane & 7) | (((lane >> 3) & 1) << 3))) * KVROW
                                     + (lane >> 4) * 16 + 128);
    const int NT = S_LEN / 64;
    const __half2 sc = __half2half2(__float2half(0.125f));

    for (;;) {
        if (tid == 0) s_item = atomicAdd(&g_ctr[2], 1u);
        __syncthreads();                 // publish s_item + fence smem reuse
        const unsigned int item = s_item;
        if (item >= ATTN_ITEMS) break;
        const int qb = (int)(item & ((S_LEN / 128) - 1));
        const int bh = (int)(item >> 4);
        const int b  = bh >> 4;
        const int h  = bh & 15;

        const __half* Qp  = qkv + ((size_t)(b * S_LEN + qb * 128)) * TDQ + h * 3 * HEAD_D;
        const __half* KVb = qkv + ((size_t)(b * S_LEN)) * TDQ + h * 3 * HEAD_D + HEAD_D;

        auto ld_tile = [&](int kt, int st) {
            const int k0 = kt * 64;
            const uint32_t sb = smb + Q_ARR + st * KV_STAGE;
            #pragma unroll
            for (int rep = 0; rep < 4; rep++) {
                int idx = tid + rep * 256;        // 0..1023
                int row = idx >> 4;               // 0..63
                int ch  = idx & 15;               // 16 x 16B = 256B (K then V)
                CP_ASYNC16(sb + row * KVROW + ch * 16,
                           KVb + (size_t)(k0 + row) * TDQ + ch * 8);
            }
        };

        // group 0: Q + tile 0; group 1: tile 1
        #pragma unroll
        for (int rep = 0; rep < 4; rep++) {
            int idx = tid + rep * 256;
            int row = idx >> 3;
            int ch  = idx & 7;
            CP_ASYNC16(smb + row * QROW + ch * 16, Qp + (size_t)row * TDQ + ch * 8);
        }
        ld_tile(0, 0);
        CP_COMMIT();
        ld_tile(1, 1);
        CP_COMMIT();

        CP_WAIT1();
        __syncthreads();

        uint32_t qf[4][4];
        #pragma unroll
        for (int kk = 0; kk < 4; kk++) {
            ldsm4(qf[kk], smb + qbase_off + kk * 32);
            #pragma unroll
            for (int r = 0; r < 4; r++) {
                __half2 hv = *(__half2*)&qf[kk][r];
                hv = __hmul2(hv, sc);
                qf[kk][r] = *(uint32_t*)&hv;
            }
        }

        float o[8][4];
        #pragma unroll
        for (int nf = 0; nf < 8; nf++)
            #pragma unroll
            for (int v = 0; v < 4; v++) o[nf][v] = 0.f;
        float m0 = -1e30f, m1 = -1e30f, l0 = 0.f, l1 = 0.f;

        int st = 0;
        for (int kt = 0; kt < NT; kt++) {
            if (kt < NT - 1) { CP_WAIT1(); } else { CP_WAIT0(); }
            __syncthreads();
            if (kt + 2 < NT) {
                int s2 = st + 2; if (s2 >= 3) s2 -= 3;
                ld_tile(kt + 2, s2);
                CP_COMMIT();
            }

            const uint32_t base_kv = smb + Q_ARR + st * KV_STAGE;

            float s_[8][4];
            #pragma unroll
            for (int nf = 0; nf < 8; nf++)
                #pragma unroll
                for (int v = 0; v < 4; v++) s_[nf][v] = 0.f;

            #pragma unroll
            for (int np = 0; np < 4; np++) {
                #pragma unroll
                for (int kk = 0; kk < 4; kk++) {
                    uint32_t kb[4];
                    ldsm4(kb, base_kv + bo_k + np * 16 * KVROW + kk * 32);
                    mma16816h(s_[2 * np],     qf[kk], kb[0], kb[2]);
                    mma16816h(s_[2 * np + 1], qf[kk], kb[1], kb[3]);
                }
            }

            float tm0 = -1e30f, tm1 = -1e30f;
            #pragma unroll
            for (int nf = 0; nf < 8; nf++) {
                tm0 = fmaxf(tm0, fmaxf(s_[nf][0], s_[nf][1]));
                tm1 = fmaxf(tm1, fmaxf(s_[nf][2], s_[nf][3]));
            }
            tm0 = fmaxf(tm0, __shfl_xor_sync(0xffffffffu, tm0, 1));
            tm0 = fmaxf(tm0, __shfl_xor_sync(0xffffffffu, tm0, 2));
            tm1 = fmaxf(tm1, __shfl_xor_sync(0xffffffffu, tm1, 1));
            tm1 = fmaxf(tm1, __shfl_xor_sync(0xffffffffu, tm1, 2));

            const float mn0 = fmaxf(m0, tm0);
            const float mn1 = fmaxf(m1, tm1);
            const float a0 = __expf(m0 - mn0);
            const float a1 = __expf(m1 - mn1);
            m0 = mn0; m1 = mn1;

            float sum0 = 0.f, sum1 = 0.f;
            #pragma unroll
            for (int nf = 0; nf < 8; nf++) {
                s_[nf][0] = __expf(s_[nf][0] - m0);
                s_[nf][1] = __expf(s_[nf][1] - m0);
                s_[nf][2] = __expf(s_[nf][2] - m1);
                s_[nf][3] = __expf(s_[nf][3] - m1);
                sum0 += s_[nf][0] + s_[nf][1];
                sum1 += s_[nf][2] + s_[nf][3];
            }
            sum0 += __shfl_xor_sync(0xffffffffu, sum0, 1);
            sum0 += __shfl_xor_sync(0xffffffffu, sum0, 2);
            sum1 += __shfl_xor_sync(0xffffffffu, sum1, 1);
            sum1 += __shfl_xor_sync(0xffffffffu, sum1, 2);
            l0 = l0 * a0 + sum0;
            l1 = l1 * a1 + sum1;

            #pragma unroll
            for (int nf = 0; nf < 8; nf++) {
                o[nf][0] *= a0; o[nf][1] *= a0;
                o[nf][2] *= a1; o[nf][3] *= a1;
            }

            uint32_t pa[4][4];
            #pragma unroll
            for (int kk = 0; kk < 4; kk++) {
                const int n0 = 2 * kk, n1 = 2 * kk + 1;
                pa[kk][0] = pack_h2(s_[n0][0], s_[n0][1]);
                pa[kk][1] = pack_h2(s_[n0][2], s_[n0][3]);
                pa[kk][2] = pack_h2(s_[n1][0], s_[n1][1]);
                pa[kk][3] = pack_h2(s_[n1][2], s_[n1][3]);
            }

            #pragma unroll
            for (int dd = 0; dd < 4; dd++) {
                #pragma unroll
                for (int kk = 0; kk < 4; kk++) {
                    uint32_t vb[4];
                    ldsm4t(vb, base_kv + bo_v + kk * 16 * KVROW + dd * 32);
                    mma16816h(o[2 * dd],     pa[kk], vb[0], vb[1]);
                    mma16816h(o[2 * dd + 1], pa[kk], vb[2], vb[3]);
                }
            }

            if (++st == 3) st = 0;
        }

        const float inv0 = 1.f / l0;
        const float inv1 = 1.f / l1;
        const int r0 = qb * 128 + wid * 16 + (lane >> 2);
        const size_t tok0 = (size_t)(b * S_LEN + r0) * D_MODEL;
        const size_t tok1 = (size_t)(b * S_LEN + r0 + 8) * D_MODEL;
        #pragma unroll
        for (int nf = 0; nf < 8; nf++) {
            const int col = h * HEAD_D + nf * 8 + (lane & 3) * 2;
            *(uint32_t*)(outp + tok0 + col) = pack_h2(o[nf][0] * inv0, o[nf][1] * inv0);
            *(uint32_t*)(outp + tok1 + col) = pack_h2(o[nf][2] * inv1, o[nf][3] * inv1);
        }
    }
}

// ---------------------------------------------------------------------------
extern "C" void kernel_launch(void* const* d_in, const int* in_sizes, int n_in,
                              void* d_out, int out_size)
{
    const float* x     = (const float*)d_in[0];
    const float* w_qkv = (const float*)d_in[1];
    const float* b_qkv = (const float*)d_in[2];
    const float* w_o   = (const float*)d_in[3];
    const float* b_o   = (const float*)d_in[4];
    float* out = (float*)d_out;

    __half *x16, *wq16, *wo16, *qkv16, *at16;
    cudaGetSymbolAddress((void**)&x16,   g_x16);
    cudaGetSymbolAddress((void**)&wq16,  g_wq16);
    cudaGetSymbolAddress((void**)&wo16,  g_wo16);
    cudaGetSymbolAddress((void**)&qkv16, g_qkv16);
    cudaGetSymbolAddress((void**)&at16,  g_at16);

    cudaFuncSetAttribute(gemm_hmma, cudaFuncAttributeMaxDynamicSharedMemorySize, GEMM_SMEM);
    cudaFuncSetAttribute(attn_mma,  cudaFuncAttributeMaxDynamicSharedMemorySize, ATTN_SMEM);

    // fused fp32 -> fp16 converts + counter reset
    cvt16_all<<<(N4_TOTAL + 255) / 256, 256>>>(
        (const float4*)x, (const float4*)w_qkv, (const float4*)w_o,
        (uint2*)x16, (uint2*)wq16, (uint2*)wo16);

    // 1) QKV projection -> fp16 (persistent, counter 0)
    {
        int ntiles = (M_ROWS / 128) * (TDQ / 128);     // 1536
        gemm_hmma<<<ntiles, 256, GEMM_SMEM>>>(x16, wq16, b_qkv, qkv16,
                                              M_ROWS, TDQ, KDIM, 1, 0);
    }
    // 2) persistent tensor-core flash attention -> fp16 [token][1024]
    {
        attn_mma<<<ATTN_ITEMS, 256, ATTN_SMEM>>>(qkv16, at16);
    }
    // 3) output projection -> fp32 (persistent, counter 1)
    {
        int ntiles = (M_ROWS / 128) * (D_MODEL / 128); // 512
        gemm_hmma<<<ntiles, 256, GEMM_SMEM>>>(at16, wo16, b_o, out,
                                              M_ROWS, D_MODEL, KDIM, 0, 1);
    }
}